// round 11
// baseline (speedup 1.0000x reference)
#include <cuda_runtime.h>
#include <cuda_fp16.h>

#define N_NODES 50000
#define N_EDGES 800000

// Scratch. q,k stored as fp16 in transposed-row layout: g_qh[node*64 + d*8 + h]
// so the 8 threads of one edge gather a full coalesced 128B line per node.
__device__ __half g_qh[N_NODES * 64];
__device__ __half g_kh[N_NODES * 64];
__device__ float  g_segsum[N_NODES * 8];
__device__ int    g_ticket;   // work-queue cursor, memset to 0 each launch

typedef unsigned long long u64;

__device__ __forceinline__ void fma2(u64 &d, u64 a, u64 b) {
    asm("fma.rn.f32x2 %0, %1, %2, %0;" : "+l"(d) : "l"(a), "l"(b));
}
__device__ __forceinline__ u64 pk2s(float a) {
    u64 r; asm("mov.b64 %0, {%1, %1};" : "=l"(r) : "f"(a)); return r;
}
__device__ __forceinline__ void unpk2(u64 a, float &x, float &y) {
    asm("mov.b64 {%0, %1}, %2;" : "=f"(x), "=f"(y) : "l"(a));
}

// Fused QKV projection. Dynamic smem = 41984 B (5 CTAs/SM):
//   [0)      sWqk[4096]  float2 {wq,wk} interleaved
//   [32768B) sxT[64][36] x tile transposed (stride 36 -> 16B-aligned LDS.128)
// Wv read via uniform __ldg (L1-resident). Tiles pulled off a global atomic
// work queue for perfect load balance (previous static 740-CTA split left a
// 40% tail: 2.11 tiles/CTA).
// Thread (g,col): rows 8g..8g+7 as 4 row-pairs, column col.
// q,k written fp16 with in-row transpose perm: out column = (col%8)*8 + col/8.
extern __shared__ float dsm[];
__global__ void __launch_bounds__(256, 5)
qkv_kernel(const float* __restrict__ x,
           const float* __restrict__ Wq, const float* __restrict__ bq,
           const float* __restrict__ Wk, const float* __restrict__ bk,
           const float* __restrict__ Wv, const float* __restrict__ bv,
           float* __restrict__ vout) {
    float2* sWqk = (float2*)dsm;       // 4096 float2
    float*  sxT  = dsm + 8192;         // 64*36
    __shared__ int s_tile;

    int tid = threadIdx.x;
    for (int i = tid; i < 4096; i += 256)
        sWqk[i] = make_float2(Wq[i], Wk[i]);

    int col = tid & 63;
    int g   = tid >> 6;      // 0..3
    int r0t = g * 8;         // local row base
    int pcol = (col & 7) * 8 + (col >> 3);  // transposed column for q,k

    float bqv = __ldg(&bq[col]);
    float bkv = __ldg(&bk[col]);
    float bvv = __ldg(&bv[col]);

    const int n_tiles = (N_NODES + 31) / 32;  // 1563
    while (true) {
        __syncthreads();   // protect s_tile reuse + sxT reuse
        if (tid == 0) s_tile = atomicAdd(&g_ticket, 1);
        __syncthreads();
        int tile = s_tile;
        if (tile >= n_tiles) break;
        int row0 = tile * 32;

        for (int i = tid; i < 32 * 64; i += 256) {
            int r = i >> 6, c = i & 63;
            sxT[c * 36 + r] = (row0 + r < N_NODES) ? x[(row0 + r) * 64 + c] : 0.0f;
        }
        __syncthreads();

        u64 aq[4] = {0,0,0,0}, ak[4] = {0,0,0,0}, av[4] = {0,0,0,0};
        #pragma unroll 8
        for (int kk = 0; kk < 64; kk++) {
            float2 wqk = sWqk[kk * 64 + col];       // one LDS.64
            float  wvs = __ldg(&Wv[kk * 64 + col]); // L1 hit
            u64 wq2 = pk2s(wqk.x);
            u64 wk2 = pk2s(wqk.y);
            u64 wv2 = pk2s(wvs);
            const uint4* xp = (const uint4*)&sxT[kk * 36 + r0t];
            uint4 xa = xp[0], xb = xp[1];           // two LDS.128 (warp-broadcast)
            u64 x0 = ((u64)xa.y << 32) | xa.x;
            u64 x1 = ((u64)xa.w << 32) | xa.z;
            u64 x2 = ((u64)xb.y << 32) | xb.x;
            u64 x3 = ((u64)xb.w << 32) | xb.z;
            fma2(aq[0], x0, wq2); fma2(ak[0], x0, wk2); fma2(av[0], x0, wv2);
            fma2(aq[1], x1, wq2); fma2(ak[1], x1, wk2); fma2(av[1], x1, wv2);
            fma2(aq[2], x2, wq2); fma2(ak[2], x2, wk2); fma2(av[2], x2, wv2);
            fma2(aq[3], x3, wq2); fma2(ak[3], x3, wk2); fma2(av[3], x3, wv2);
        }
        #pragma unroll
        for (int j = 0; j < 4; j++) {
            float q0, q1, k0, k1, v0, v1;
            unpk2(aq[j], q0, q1);
            unpk2(ak[j], k0, k1);
            unpk2(av[j], v0, v1);
            int row = row0 + r0t + 2 * j;
            if (row < N_NODES) {
                g_qh[row * 64 + pcol] = __float2half(q0 + bqv);
                g_kh[row * 64 + pcol] = __float2half(k0 + bkv);
                vout[row * 64 + col]  = v0 + bvv;
            }
            if (row + 1 < N_NODES) {
                g_qh[(row + 1) * 64 + pcol] = __float2half(q1 + bqv);
                g_kh[(row + 1) * 64 + pcol] = __float2half(k1 + bkv);
                vout[(row + 1) * 64 + col]  = v1 + bvv;
            }
        }
    }
}

// Fused: prods + exp + segment-sum. Thread = (edge, d). fp16 q/k: the 8
// threads of one edge read one full 128B line per node (fully coalesced).
__global__ void prods_exp_kernel(const int* __restrict__ edge,
                                 float* __restrict__ prods_out) {
    int idx = blockIdx.x * blockDim.x + threadIdx.x;
    if (idx >= N_EDGES * 8) return;
    int e = idx >> 3;
    int d = idx & 7;
    int s = __ldg(&edge[e]);
    int t = __ldg(&edge[N_EDGES + e]);
    uint4 qv = *(const uint4*)(g_qh + s * 64 + d * 8);
    uint4 kv = *(const uint4*)(g_kh + t * 64 + d * 8);
    const __half2* qh = (const __half2*)&qv;
    const __half2* kh = (const __half2*)&kv;
    float acc = 0.0f;
    #pragma unroll
    for (int i = 0; i < 4; i++) {
        float2 qf = __half22float2(qh[i]);
        float2 kf = __half22float2(kh[i]);
        acc += qf.x * kf.x + qf.y * kf.y;
    }
    float p = acc * 0.35355339059327373f;  // 1/sqrt(8)
    prods_out[idx] = p;
    float ex = __expf(p);  // no max subtraction: p ~ N(0,1), cannot overflow
    atomicAdd(&g_segsum[t * 8 + d], ex);
}

// One edge per thread: att = exp(prods) / (segsum + 1e-16), vectorized.
__global__ void norm_kernel(const int* __restrict__ edge,
                            const float* __restrict__ prods,
                            float* __restrict__ att) {
    int e = blockIdx.x * blockDim.x + threadIdx.x;
    if (e >= N_EDGES) return;
    int t = __ldg(&edge[N_EDGES + e]);
    const float4* sp = (const float4*)&g_segsum[t * 8];
    float4 s0 = sp[0], s1 = sp[1];
    const float4* pp = (const float4*)&prods[(size_t)e * 8];
    float4 p0 = pp[0], p1 = pp[1];
    float4 a0, a1;
    a0.x = __fdividef(__expf(p0.x), s0.x + 1e-16f);
    a0.y = __fdividef(__expf(p0.y), s0.y + 1e-16f);
    a0.z = __fdividef(__expf(p0.z), s0.z + 1e-16f);
    a0.w = __fdividef(__expf(p0.w), s0.w + 1e-16f);
    a1.x = __fdividef(__expf(p1.x), s1.x + 1e-16f);
    a1.y = __fdividef(__expf(p1.y), s1.y + 1e-16f);
    a1.z = __fdividef(__expf(p1.z), s1.z + 1e-16f);
    a1.w = __fdividef(__expf(p1.w), s1.w + 1e-16f);
    float4* ap = (float4*)&att[(size_t)e * 8];
    ap[0] = a0;
    ap[1] = a1;
}

extern "C" void kernel_launch(void* const* d_in, const int* in_sizes, int n_in,
                              void* d_out, int out_size) {
    const float* x    = (const float*)d_in[0];
    const float* Wq   = (const float*)d_in[1];
    const float* bq   = (const float*)d_in[2];
    const float* Wk   = (const float*)d_in[3];
    const float* bk   = (const float*)d_in[4];
    const float* Wv   = (const float*)d_in[5];
    const float* bv   = (const float*)d_in[6];
    const int*   edge = (const int*)d_in[7];

    float* out   = (float*)d_out;
    float* att   = out;                                               // [E*8]
    float* vout  = out + (size_t)N_EDGES * 8;                         // [N*64]
    float* prods = out + (size_t)N_EDGES * 8 + (size_t)N_NODES * 64;  // [E*8]

    const int QKV_SMEM = (8192 + 64 * 36) * 4;  // 41984 bytes -> 5 CTAs/SM
    static void* segsum_ptr = nullptr;
    static void* ticket_ptr = nullptr;
    if (!segsum_ptr) {
        cudaFuncSetAttribute(qkv_kernel, cudaFuncAttributeMaxDynamicSharedMemorySize, QKV_SMEM);
        cudaGetSymbolAddress(&segsum_ptr, g_segsum);
        cudaGetSymbolAddress(&ticket_ptr, g_ticket);
    }

    // Zero segment sums + work-queue cursor (graph-capturable memset nodes)
    cudaMemsetAsync(segsum_ptr, 0, N_NODES * 8 * sizeof(float), 0);
    cudaMemsetAsync(ticket_ptr, 0, sizeof(int), 0);

    qkv_kernel<<<740, 256, QKV_SMEM>>>(x, Wq, bq, Wk, bk, Wv, bv, vout);

    int n_ed = N_EDGES * 8;
    prods_exp_kernel<<<(n_ed + 255) / 256, 256>>>(edge, prods);
    norm_kernel<<<(N_EDGES + 255) / 256, 256>>>(edge, prods, att);
}

// round 15
// speedup vs baseline: 1.3379x; 1.3379x over previous
#include <cuda_runtime.h>
#include <cuda_fp16.h>

#define N_NODES 50000
#define N_EDGES 800000

// Scratch. q,k stored as fp16 in transposed-row layout: g_qh[node*64 + d*8 + h]
// so the 8 threads of one edge gather a full coalesced 128B line per node.
__device__ __half g_qh[N_NODES * 64];
__device__ __half g_kh[N_NODES * 64];
__device__ float  g_segsum[N_NODES * 8];

typedef unsigned long long u64;

__device__ __forceinline__ void fma2(u64 &d, u64 a, u64 b) {
    asm("fma.rn.f32x2 %0, %1, %2, %0;" : "+l"(d) : "l"(a), "l"(b));
}
__device__ __forceinline__ u64 pk2s(float a) {
    u64 r; asm("mov.b64 %0, {%1, %1};" : "=l"(r) : "f"(a)); return r;
}
__device__ __forceinline__ void unpk2(u64 a, float &x, float &y) {
    asm("mov.b64 {%0, %1}, %2;" : "=f"(x), "=f"(y) : "l"(a));
}

// Fused QKV projection. Dynamic smem = 41984 B (5 CTAs/SM):
//   [0)       sWqk[4096] float2 {wq,wk} interleaved -> one LDS.64 per kk
//   [32768B)  sxT[64][36] x tile transposed (stride 36 -> 16B-aligned LDS.128)
// Wv read via uniform __ldg (16KB, L1-resident after first tile).
// Grid 521, stride-521 tiling: 1563 tiles = 521 x exactly 3 -> zero tail.
// Thread (g,col): rows 8g..8g+7 as 4 row-pairs, column col. x row-pairs are
// loaded as ulonglong2 (LDS.128 straight into u64 pairs, no reassembly).
// q,k written fp16 with in-row transpose perm: out column = (col%8)*8 + col/8.
extern __shared__ float dsm[];
__global__ void __launch_bounds__(256, 5)
qkv_kernel(const float* __restrict__ x,
           const float* __restrict__ Wq, const float* __restrict__ bq,
           const float* __restrict__ Wk, const float* __restrict__ bk,
           const float* __restrict__ Wv, const float* __restrict__ bv,
           float* __restrict__ vout) {
    float2* sWqk = (float2*)dsm;       // 4096 float2
    float*  sxT  = dsm + 8192;         // 64*36

    int tid = threadIdx.x;
    for (int i = tid; i < 4096; i += 256)
        sWqk[i] = make_float2(Wq[i], Wk[i]);

    int col = tid & 63;
    int g   = tid >> 6;      // 0..3
    int r0t = g * 8;         // local row base
    int pcol = (col & 7) * 8 + (col >> 3);  // transposed column for q,k

    float bqv = __ldg(&bq[col]);
    float bkv = __ldg(&bk[col]);
    float bvv = __ldg(&bv[col]);

    const int n_tiles = (N_NODES + 31) / 32;  // 1563 = 3 * 521
    for (int tile = blockIdx.x; tile < n_tiles; tile += gridDim.x) {
        int row0 = tile * 32;
        __syncthreads();   // protect sxT reuse (and first-iter weight readiness)
        for (int i = tid; i < 32 * 64; i += 256) {
            int r = i >> 6, c = i & 63;
            sxT[c * 36 + r] = (row0 + r < N_NODES) ? x[(row0 + r) * 64 + c] : 0.0f;
        }
        __syncthreads();

        u64 aq[4] = {0,0,0,0}, ak[4] = {0,0,0,0}, av[4] = {0,0,0,0};
        #pragma unroll 8
        for (int kk = 0; kk < 64; kk++) {
            float2 wqk = sWqk[kk * 64 + col];        // LDS.64
            float  wvs = __ldg(&Wv[kk * 64 + col]);  // L1 hit
            u64 wq2 = pk2s(wqk.x);
            u64 wk2 = pk2s(wqk.y);
            u64 wv2 = pk2s(wvs);
            const ulonglong2* xp = (const ulonglong2*)&sxT[kk * 36 + r0t];
            ulonglong2 xa = xp[0], xb = xp[1];       // 2x LDS.128 (warp-broadcast)
            fma2(aq[0], xa.x, wq2); fma2(ak[0], xa.x, wk2); fma2(av[0], xa.x, wv2);
            fma2(aq[1], xa.y, wq2); fma2(ak[1], xa.y, wk2); fma2(av[1], xa.y, wv2);
            fma2(aq[2], xb.x, wq2); fma2(ak[2], xb.x, wk2); fma2(av[2], xb.x, wv2);
            fma2(aq[3], xb.y, wq2); fma2(ak[3], xb.y, wk2); fma2(av[3], xb.y, wv2);
        }
        #pragma unroll
        for (int j = 0; j < 4; j++) {
            float q0, q1, k0, k1, v0, v1;
            unpk2(aq[j], q0, q1);
            unpk2(ak[j], k0, k1);
            unpk2(av[j], v0, v1);
            int row = row0 + r0t + 2 * j;
            if (row < N_NODES) {
                g_qh[row * 64 + pcol] = __float2half(q0 + bqv);
                g_kh[row * 64 + pcol] = __float2half(k0 + bkv);
                vout[row * 64 + col]  = v0 + bvv;
            }
            if (row + 1 < N_NODES) {
                g_qh[(row + 1) * 64 + pcol] = __float2half(q1 + bqv);
                g_kh[(row + 1) * 64 + pcol] = __float2half(k1 + bkv);
                vout[(row + 1) * 64 + col]  = v1 + bvv;
            }
        }
    }
}

// Fused: prods + exp + segment-sum. Thread = (edge, d). fp16 q/k: the 8
// threads of one edge read one full 128B line per node (fully coalesced).
__global__ void prods_exp_kernel(const int* __restrict__ edge,
                                 float* __restrict__ prods_out) {
    int idx = blockIdx.x * blockDim.x + threadIdx.x;
    if (idx >= N_EDGES * 8) return;
    int e = idx >> 3;
    int d = idx & 7;
    int s = __ldg(&edge[e]);
    int t = __ldg(&edge[N_EDGES + e]);
    uint4 qv = *(const uint4*)(g_qh + s * 64 + d * 8);
    uint4 kv = *(const uint4*)(g_kh + t * 64 + d * 8);
    const __half2* qh = (const __half2*)&qv;
    const __half2* kh = (const __half2*)&kv;
    float acc = 0.0f;
    #pragma unroll
    for (int i = 0; i < 4; i++) {
        float2 qf = __half22float2(qh[i]);
        float2 kf = __half22float2(kh[i]);
        acc += qf.x * kf.x + qf.y * kf.y;
    }
    float p = acc * 0.35355339059327373f;  // 1/sqrt(8)
    prods_out[idx] = p;
    float ex = __expf(p);  // no max subtraction: p ~ N(0,1), cannot overflow
    atomicAdd(&g_segsum[t * 8 + d], ex);
}

// One edge per thread: att = exp(prods) / (segsum + 1e-16), vectorized.
__global__ void norm_kernel(const int* __restrict__ edge,
                            const float* __restrict__ prods,
                            float* __restrict__ att) {
    int e = blockIdx.x * blockDim.x + threadIdx.x;
    if (e >= N_EDGES) return;
    int t = __ldg(&edge[N_EDGES + e]);
    const float4* sp = (const float4*)&g_segsum[t * 8];
    float4 s0 = sp[0], s1 = sp[1];
    const float4* pp = (const float4*)&prods[(size_t)e * 8];
    float4 p0 = pp[0], p1 = pp[1];
    float4 a0, a1;
    a0.x = __fdividef(__expf(p0.x), s0.x + 1e-16f);
    a0.y = __fdividef(__expf(p0.y), s0.y + 1e-16f);
    a0.z = __fdividef(__expf(p0.z), s0.z + 1e-16f);
    a0.w = __fdividef(__expf(p0.w), s0.w + 1e-16f);
    a1.x = __fdividef(__expf(p1.x), s1.x + 1e-16f);
    a1.y = __fdividef(__expf(p1.y), s1.y + 1e-16f);
    a1.z = __fdividef(__expf(p1.z), s1.z + 1e-16f);
    a1.w = __fdividef(__expf(p1.w), s1.w + 1e-16f);
    float4* ap = (float4*)&att[(size_t)e * 8];
    ap[0] = a0;
    ap[1] = a1;
}

extern "C" void kernel_launch(void* const* d_in, const int* in_sizes, int n_in,
                              void* d_out, int out_size) {
    const float* x    = (const float*)d_in[0];
    const float* Wq   = (const float*)d_in[1];
    const float* bq   = (const float*)d_in[2];
    const float* Wk   = (const float*)d_in[3];
    const float* bk   = (const float*)d_in[4];
    const float* Wv   = (const float*)d_in[5];
    const float* bv   = (const float*)d_in[6];
    const int*   edge = (const int*)d_in[7];

    float* out   = (float*)d_out;
    float* att   = out;                                               // [E*8]
    float* vout  = out + (size_t)N_EDGES * 8;                         // [N*64]
    float* prods = out + (size_t)N_EDGES * 8 + (size_t)N_NODES * 64;  // [E*8]

    const int QKV_SMEM = (8192 + 64 * 36) * 4;  // 41984 bytes -> 5 CTAs/SM
    static void* segsum_ptr = nullptr;
    if (!segsum_ptr) {
        cudaFuncSetAttribute(qkv_kernel, cudaFuncAttributeMaxDynamicSharedMemorySize, QKV_SMEM);
        cudaGetSymbolAddress(&segsum_ptr, g_segsum);
    }

    // Zero segment sums (graph-capturable memset node)
    cudaMemsetAsync(segsum_ptr, 0, N_NODES * 8 * sizeof(float), 0);

    // 521 CTAs x exactly 3 tiles = 1563 tiles, zero tail
    qkv_kernel<<<521, 256, QKV_SMEM>>>(x, Wq, bq, Wk, bk, Wv, bv, vout);

    int n_ed = N_EDGES * 8;
    prods_exp_kernel<<<(n_ed + 255) / 256, 256>>>(edge, prods);
    norm_kernel<<<(N_EDGES + 255) / 256, 256>>>(edge, prods, att);
}